// round 11
// baseline (speedup 1.0000x reference)
#include <cuda_runtime.h>
#include <cstdint>

#define NATOMS 6144
#define FDIM   128
#define HDIM   64
#define NMOL   48
#define NBLK   148     // co-resident on B300(148)/GB300(152)
#define NTHR   768
#define NWARP  24
#define ASLOT  42      // exact atom slots (acnt is 41..42)
#define NPAIRS 21
#define SH0CAP 48      // TMA landing buffer rows

// Device-global scratch. Deterministic overwrites; g_qsumF/g_ready are zero at
// load and re-zeroed by the last-arriving block each replay (after all reads).
__device__ float4 g_A[NATOMS];        // pos.xyz, q_raw
__device__ float4 g_B[NATOMS];        // mu.xyz, sqrt(softplus(c6))
__device__ int    g_segs[NMOL];
__device__ int    g_sege[NMOL];
__device__ float  g_qsumF[NMOL];      // per-molecule q sums (atomic, replay-safe)
__device__ double g_partial[NBLK];
__device__ volatile int g_ready[NBLK]; // per-block phase-1 completion flags
__device__ int    g_done;              // completion ticket (self-resetting)

// ---- f32x2 packed-FMA helpers (FFMA2 on sm_100+) ---------------------------
__device__ __forceinline__ long long dupf(float w) {
    long long d; unsigned r = __float_as_uint(w);
    asm("mov.b64 %0, {%1, %1};" : "=l"(d) : "r"(r));
    return d;
}
__device__ __forceinline__ void ffma2(long long& a, long long h, long long w) {
    asm("fma.rn.f32x2 %0, %1, %2, %0;" : "+l"(a) : "l"(h), "l"(w));
}
__device__ __forceinline__ void unpack2(long long a, float& lo, float& hi) {
    unsigned l, h;
    asm("mov.b64 {%0, %1}, %2;" : "=r"(l), "=r"(h) : "l"(a));
    lo = __uint_as_float(l); hi = __uint_as_float(h);
}

__device__ __forceinline__ void tma_bulk_1d(uint32_t dst, const void* src,
                                            uint32_t bytes, uint32_t mbar) {
    asm volatile(
        "cp.async.bulk.shared::cta.global.mbarrier::complete_tx::bytes [%0], [%1], %2, [%3];"
        :: "r"(dst), "l"(src), "r"(bytes), "r"(mbar) : "memory");
}
__device__ __forceinline__ void mbar_wait0(uint32_t mb) {
    asm volatile(
        "{\n\t.reg .pred P;\n"
        "WAIT_%=:\n\t"
        "mbarrier.try_wait.parity.acquire.cta.shared::cta.b64 P, [%0], 0, 0x989680;\n\t"
        "@!P bra WAIT_%=;\n\t}"
        :: "r"(mb) : "memory");
}

// block id containing atom x (astart(b) = b*NATOMS/NBLK, floor division)
__device__ __forceinline__ int bid_of(int x) {
    return (int)(((long long)(x + 1) * NBLK - 1) / NATOMS);
}

extern "C" __global__ void __launch_bounds__(NTHR, 1) fused_kernel(
    const float* __restrict__ h0, const float* __restrict__ h1,
    const float* __restrict__ pos, const int* __restrict__ batch,
    const float* __restrict__ qW1, const float* __restrict__ qb1,
    const float* __restrict__ qW2, const float* __restrict__ qb2,
    const float* __restrict__ cW1, const float* __restrict__ cb1,
    const float* __restrict__ cW2, const float* __restrict__ cb2,
    const float* __restrict__ muW, float* __restrict__ out)
{
    extern __shared__ float smem[];
    float* sH0  = smem;                        // 48*128 = 24 KB (TMA dst; overlaid later)
    float* sWq  = smem + SH0CAP * FDIM;        // 32 KB (TMA dst)
    float* sWc  = sWq + FDIM * HDIM;           // 32 KB (TMA dst)
    float* sH0P = sWc + FDIM * HDIM;           // 21 pairs x 256 floats = 21 KB
    long long* sComb = (long long*)sH0;        // overlay: 6 grp-slots * 32 * 14 ll

    __shared__ float  sPQ[3][14];
    __shared__ float  sPC[3][14];
    __shared__ float  s_mu[ASLOT][3];
    __shared__ float  s_qp[NMOL];
    __shared__ float  s_qmean[NMOL];
    __shared__ double sDD[NWARP];
    __shared__ int    s_last, s_ms, s_me;
    __shared__ __align__(8) unsigned long long mbar[1];

    const int tid  = threadIdx.x;
    const int bid  = blockIdx.x;
    const int w    = tid >> 5;
    const int lane = tid & 31;

    const int astart = (bid * NATOMS) / NBLK;
    const int aend   = ((bid + 1) * NATOMS) / NBLK;
    const int acnt   = aend - astart;          // 41 or 42

    const uint32_t mb   = (uint32_t)__cvta_generic_to_shared(mbar);
    const uint32_t sH0u = (uint32_t)__cvta_generic_to_shared(sH0);
    const uint32_t sWqu = (uint32_t)__cvta_generic_to_shared(sWq);
    const uint32_t sWcu = (uint32_t)__cvta_generic_to_shared(sWc);

    if (tid == 0)
        asm volatile("mbarrier.init.shared.b64 [%0], 1;" :: "r"(mb) : "memory");
    if (tid < NMOL) s_qp[tid] = 0.0f;
    __syncthreads();

    // ========== Warp-specialized phase 1 ====================================
    if (w < 12) {
        // ---- TMA prologue (MLP warps only) ---------------------------------
        const uint32_t h0_bytes = (uint32_t)acnt * FDIM * 4u;
        if (tid == 0) {
            const uint32_t total = 2u * FDIM * HDIM * 4u + h0_bytes;
            asm volatile("mbarrier.arrive.expect_tx.shared.b64 _, [%0], %1;"
                         :: "r"(mb), "r"(total) : "memory");
            tma_bulk_1d(sWqu, qW1, FDIM * HDIM * 4u, mb);
            tma_bulk_1d(sWcu, cW1, FDIM * HDIM * 4u, mb);
            tma_bulk_1d(sH0u, h0 + (size_t)astart * FDIM, h0_bytes, mb);
        }
        mbar_wait0(mb);

        // ---- transform h0 -> pair-major f32x2 layout (384 threads) ---------
        for (int idx = tid; idx < ASLOT * FDIM; idx += 384) {
            const int a = idx >> 7, f = idx & 127;
            const float v = (a < acnt) ? sH0[a * FDIM + f] : 0.0f;
            sH0P[(a >> 1) * 256 + f * 2 + (a & 1)] = v;
        }
        asm volatile("bar.sync 1, 384;" ::: "memory");

        // ---- MLPs: 12 warps = 2 MLPs x 3 pair-groups x 2 f-halves ----------
        const int sec = w / 6;
        const int wl  = w % 6;
        const int pg  = wl >> 1;
        const int fh  = wl & 1;
        const float* sW = sec ? sWc : sWq;
        const float* B1 = sec ? cb1 : qb1;
        const float* W2 = sec ? cW2 : qW2;

        long long acc[7][2];
        #pragma unroll
        for (int p = 0; p < 7; p++) { acc[p][0] = 0; acc[p][1] = 0; }
        const int pb = pg * 7;

        #pragma unroll 2
        for (int f4 = fh * 16; f4 < fh * 16 + 16; f4++) {
            float2 wv[4];
            #pragma unroll
            for (int k = 0; k < 4; k++)
                wv[k] = *reinterpret_cast<const float2*>(
                    &sW[(4 * f4 + k) * HDIM + 2 * lane]);
            const long long u0w0 = dupf(wv[0].x), u1w0 = dupf(wv[0].y);
            const long long u0w1 = dupf(wv[1].x), u1w1 = dupf(wv[1].y);
            const long long u0w2 = dupf(wv[2].x), u1w2 = dupf(wv[2].y);
            const long long u0w3 = dupf(wv[3].x), u1w3 = dupf(wv[3].y);
            #pragma unroll
            for (int p = 0; p < 7; p++) {
                const double2* hp = reinterpret_cast<const double2*>(
                    &sH0P[(pb + p) * 256 + f4 * 8]);
                const double2 hA = hp[0];
                const double2 hB = hp[1];
                const long long a0 = __double_as_longlong(hA.x);
                const long long a1 = __double_as_longlong(hA.y);
                const long long a2 = __double_as_longlong(hB.x);
                const long long a3 = __double_as_longlong(hB.y);
                ffma2(acc[p][0], a0, u0w0); ffma2(acc[p][1], a0, u1w0);
                ffma2(acc[p][0], a1, u0w1); ffma2(acc[p][1], a1, u1w1);
                ffma2(acc[p][0], a2, u0w2); ffma2(acc[p][1], a2, u1w2);
                ffma2(acc[p][0], a3, u0w3); ffma2(acc[p][1], a3, u1w3);
            }
        }

        // ---- combine f-halves through smem (overlay on dead sH0) -----------
        const int slot = ((sec * 3 + pg) * 32 + lane) * 14;
        asm volatile("bar.sync 1, 384;" ::: "memory");
        if (fh == 0) {
            #pragma unroll
            for (int p = 0; p < 7; p++) {
                sComb[slot + 2 * p]     = acc[p][0];
                sComb[slot + 2 * p + 1] = acc[p][1];
            }
        }
        asm volatile("bar.sync 1, 384;" ::: "memory");
        if (fh == 1) {
            const float2 b1v = *reinterpret_cast<const float2*>(&B1[2 * lane]);
            const float2 w2v = *reinterpret_cast<const float2*>(&W2[2 * lane]);
            float v[14];
            #pragma unroll
            for (int p = 0; p < 7; p++) {
                float hA0, hB0, hA1, hB1, oA0, oB0, oA1, oB1;
                unpack2(acc[p][0], hA0, hB0);
                unpack2(acc[p][1], hA1, hB1);
                unpack2(sComb[slot + 2 * p],     oA0, oB0);
                unpack2(sComb[slot + 2 * p + 1], oA1, oB1);
                const float xA0 = hA0 + oA0 + b1v.x;
                const float xB0 = hB0 + oB0 + b1v.x;
                const float xA1 = hA1 + oA1 + b1v.y;
                const float xB1 = hB1 + oB1 + b1v.y;
                const float sA0 = xA0 * __fdividef(1.0f, 1.0f + __expf(-xA0)) * w2v.x;
                const float sB0 = xB0 * __fdividef(1.0f, 1.0f + __expf(-xB0)) * w2v.x;
                const float sA1 = xA1 * __fdividef(1.0f, 1.0f + __expf(-xA1)) * w2v.y;
                const float sB1 = xB1 * __fdividef(1.0f, 1.0f + __expf(-xB1)) * w2v.y;
                v[2 * p]     = sA0 + sA1;
                v[2 * p + 1] = sB0 + sB1;
            }
            #pragma unroll
            for (int k = 0; k < 14; k++) {
                #pragma unroll
                for (int o = 16; o > 0; o >>= 1)
                    v[k] += __shfl_down_sync(0xffffffffu, v[k], o);
            }
            if (lane == 0) {
                float (*dst)[14] = sec ? sPC : sPQ;
                #pragma unroll
                for (int k = 0; k < 14; k++) dst[pg][k] = v[k];
            }
        }
    } else {
        // ---- warps 12/13: molecule-boundary scans (for neighbor sync) ------
        if (w == 12) {
            const int b0 = batch[astart];
            int posn = astart;
            while (true) {
                const int x = posn - 1 - lane;
                const int v = (x >= 0) ? batch[x] : -1;
                const unsigned m = __ballot_sync(0xffffffffu, v != b0);
                if (m) { if (lane == 0) s_ms = posn - (__ffs(m) - 1); break; }
                posn -= 32;
            }
        } else if (w == 13) {
            const int b1 = batch[aend - 1];
            int posn = aend;
            while (true) {
                const int x = posn + lane;
                const int v = (x < NATOMS) ? batch[x] : -1;
                const unsigned m = __ballot_sync(0xffffffffu, v != b1);
                if (m) { if (lane == 0) s_me = posn + (__ffs(m) - 1); break; }
                posn += 32;
            }
        }
        // ---- mu warps (12-23): h1 from global (overlaps TMA + MLP) ---------
        const float4 mw4 = *reinterpret_cast<const float4*>(muW + lane * 4);
        for (int loc = w - 12; loc < acnt; loc += 12) {
            const float* hr = h1 + (size_t)(astart + loc) * 3 * FDIM;
            float m[3];
            #pragma unroll
            for (int d = 0; d < 3; d++) {
                const float4 a = *reinterpret_cast<const float4*>(hr + d * FDIM + lane * 4);
                m[d] = a.x * mw4.x + a.y * mw4.y + a.z * mw4.z + a.w * mw4.w;
            }
            #pragma unroll
            for (int o = 16; o > 0; o >>= 1) {
                m[0] += __shfl_down_sync(0xffffffffu, m[0], o);
                m[1] += __shfl_down_sync(0xffffffffu, m[1], o);
                m[2] += __shfl_down_sync(0xffffffffu, m[2], o);
            }
            if (lane == 0) { s_mu[loc][0] = m[0]; s_mu[loc][1] = m[1]; s_mu[loc][2] = m[2]; }
        }
    }
    __syncthreads();

    // ---- Pack per-atom data + segment boundaries + molecule q partials -----
    if (tid < acnt) {
        const int grp = tid / 14, idx = tid % 14;
        const float qv  = sPQ[grp][idx] + qb2[0];
        const float cv  = sPC[grp][idx] + cb2[0];
        const float sp  = fmaxf(cv, 0.0f) + log1pf(__expf(-fabsf(cv)));
        const int i = astart + tid;
        const int b = batch[i];
        g_A[i] = make_float4(pos[3 * i], pos[3 * i + 1], pos[3 * i + 2], qv);
        g_B[i] = make_float4(s_mu[tid][0], s_mu[tid][1], s_mu[tid][2], sqrtf(sp));
        if (i == 0 || batch[i - 1] != b) g_segs[b] = i;
        if (i == NATOMS - 1 || batch[i + 1] != b) g_sege[b] = i + 1;
        atomicAdd(&s_qp[b], qv);
    }
    __syncthreads();
    if (tid < NMOL && s_qp[tid] != 0.0f) atomicAdd(&g_qsumF[tid], s_qp[tid]);

    // ---- Signal readiness, then wait only on producer neighborhood ---------
    __threadfence();
    __syncthreads();                           // all writes (incl. qsum atomics) issued
    if (tid == 0) g_ready[bid] = 1;            // volatile store after fence

    const int lo = bid_of(s_ms);
    const int hi = bid_of(s_me - 1);
    if (tid <= hi - lo) {
        while (g_ready[lo + tid] == 0) { }
        __threadfence();                       // acquire producers' writes
    }
    __syncthreads();

    // ---- qmean for this block's molecules ----------------------------------
    const int bfirst = batch[astart];
    const int blast  = batch[aend - 1];
    if (tid <= blast - bfirst) {
        const int m = bfirst + tid;
        const int cnt = g_sege[m] - g_segs[m];
        s_qmean[m] = (cnt > 0) ? g_qsumF[m] / (float)cnt : 0.0f;
    }
    __syncthreads();

    // ---- Pairwise energy: block-local atoms, mirror-balanced ---------------
    double acc2 = 0.0;
    if (w <= acnt - 1 - w) {
        #pragma unroll
        for (int half = 0; half < 2; half++) {
            const int loc = half ? (acnt - 1 - w) : w;
            if (half && loc == w) break;       // odd middle already done
            const int i  = astart + loc;
            const int b  = batch[i];
            const int e0 = g_sege[b];
            const float qm = s_qmean[b];

            const float4 Ai = g_A[i];
            const float4 Bi = g_B[i];
            const float qi = Ai.w - qm;

            float facc = 0.0f;
            int j = i + 1 + lane;
            if (j < e0) {
                float4 Aj = g_A[j];
                float4 Bj = g_B[j];
                while (true) {
                    const int jn = j + 32;
                    float4 An, Bn;
                    if (jn < e0) { An = g_A[jn]; Bn = g_B[jn]; }

                    const float dx = Ai.x - Aj.x;
                    const float dy = Ai.y - Aj.y;
                    const float dz = Ai.z - Aj.z;
                    const float d2r  = dx * dx + dy * dy + dz * dz;
                    const float d2   = d2r + 1e-8f;
                    const float invd = rsqrtf(d2);                    // MUFU 1
                    const float dist = d2 * invd;

                    const float qj    = Aj.w - qm;
                    const float taper = 1.0f - __expf(-0.5f * dist);  // MUFU 2
                    const float ec    = qi * qj * invd * taper * 14.399f;

                    const float r6    = d2r * d2r * d2r;
                    const float aden  = r6 + 20.0f;
                    const float bden  = d2r * dist + 10.0f;
                    const float invab = __fdividef(1.0f, aden * bden); // MUFU 3

                    const float ev = -Bi.w * Bj.w * (invab * bden);

                    const float mumu = Bi.x * Bj.x + Bi.y * Bj.y + Bi.z * Bj.z;
                    const float di   = (Bi.x * dx + Bi.y * dy + Bi.z * dz) * invd;
                    const float dj   = (Bj.x * dx + Bj.y * dy + Bj.z * dz) * invd;
                    const float ed   = (mumu - 3.0f * di * dj) * (invab * aden);

                    facc += ec + ev + ed;

                    if (jn >= e0) break;
                    Aj = An; Bj = Bn; j = jn;
                }
            }
            acc2 += (double)facc;
        }
    }

    #pragma unroll
    for (int o = 16; o > 0; o >>= 1)
        acc2 += __shfl_down_sync(0xffffffffu, acc2, o);
    if (lane == 0) sDD[w] = acc2;
    __syncthreads();
    if (tid == 0) {
        double ts = 0.0;
        #pragma unroll
        for (int k = 0; k < NWARP; k++) ts += sDD[k];
        g_partial[bid] = ts;
        __threadfence();
        s_last = (atomicAdd(&g_done, 1) == NBLK - 1) ? 1 : 0;
    }
    __syncthreads();

    // ---- Last-arriving block: reset replay state, reduce, write output -----
    if (s_last) {
        __threadfence();
        if (tid == 0) g_done = 0;
        if (tid < NMOL) g_qsumF[tid] = 0.0f;   // all readers finished (ticket)
        if (tid < NBLK) g_ready[tid] = 0;      // all spins finished (ticket)
        double v = (tid < NBLK) ? g_partial[tid] : 0.0;
        #pragma unroll
        for (int o = 16; o > 0; o >>= 1)
            v += __shfl_down_sync(0xffffffffu, v, o);
        if (lane == 0 && w < 5) sDD[w] = v;
        __syncthreads();
        if (tid == 0) {
            double tot = 0.0;
            #pragma unroll
            for (int k = 0; k < 5; k++) tot += sDD[k];
            out[0] = (float)tot;               // LONG_RANGE_SCALE = 1.0
        }
    }
}

// ---------------------------------------------------------------------------
extern "C" void kernel_launch(void* const* d_in, const int* in_sizes, int n_in,
                              void* d_out, int out_size) {
    const float* h0    = (const float*)d_in[0];
    const float* h1    = (const float*)d_in[1];
    const float* pos   = (const float*)d_in[2];
    const int*   batch = (const int*)  d_in[3];
    const float* qW1   = (const float*)d_in[4];
    const float* qb1   = (const float*)d_in[5];
    const float* qW2   = (const float*)d_in[6];
    const float* qb2   = (const float*)d_in[7];
    const float* cW1   = (const float*)d_in[8];
    const float* cb1   = (const float*)d_in[9];
    const float* cW2   = (const float*)d_in[10];
    const float* cb2   = (const float*)d_in[11];
    const float* muW   = (const float*)d_in[12];

    const int smem_bytes = (SH0CAP * FDIM + 2 * FDIM * HDIM + NPAIRS * 256)
                           * (int)sizeof(float);   // ~109 KB
    cudaFuncSetAttribute(fused_kernel,
                         cudaFuncAttributeMaxDynamicSharedMemorySize, smem_bytes);
    fused_kernel<<<NBLK, NTHR, smem_bytes>>>(
        h0, h1, pos, batch,
        qW1, qb1, qW2, qb2,
        cW1, cb1, cW2, cb2,
        muW, (float*)d_out);
}

// round 12
// speedup vs baseline: 1.0437x; 1.0437x over previous
#include <cuda_runtime.h>
#include <cstdint>

#define NATOMS 6144
#define FDIM   128
#define HDIM   64
#define NMOL   48
#define NBLK   148     // co-resident on B300(148)/GB300(152)
#define NTHR   768
#define NWARP  24
#define NWTOT  (NBLK * NWARP)
#define ASLOT  42      // padded atom slots (acnt is 41..42)
#define NPAIRS 21

// Device-global scratch. Deterministic overwrites; g_qsumF is zero at load and
// re-zeroed by the last-arriving block each replay (after all reads).
__device__ float4 g_A[NATOMS];        // pos.xyz, q_raw
__device__ float4 g_B[NATOMS];        // mu.xyz, sqrt(softplus(c6))
__device__ int    g_segs[NMOL];
__device__ int    g_sege[NMOL];
__device__ float  g_qsumF[NMOL];      // per-molecule q sums (atomic, replay-safe)
__device__ double g_partial[NBLK];
__device__ volatile int g_sense;
__device__ int    g_count;
__device__ int    g_done;

__device__ __forceinline__ void grid_barrier() {
    __syncthreads();
    if (threadIdx.x == 0) {
        int s = g_sense;
        __threadfence();
        if (atomicAdd(&g_count, 1) == NBLK - 1) {
            g_count = 0;
            __threadfence();
            g_sense = s ^ 1;
        } else {
            while (g_sense == s) { }
        }
    }
    __syncthreads();
    __threadfence();
}

// ---- f32x2 packed-FMA helpers (FFMA2 on sm_100+) ---------------------------
__device__ __forceinline__ long long dupf(float w) {
    long long d; unsigned r = __float_as_uint(w);
    asm("mov.b64 %0, {%1, %1};" : "=l"(d) : "r"(r));
    return d;
}
__device__ __forceinline__ void ffma2(long long& a, long long h, long long w) {
    asm("fma.rn.f32x2 %0, %1, %2, %0;" : "+l"(a) : "l"(h), "l"(w));
}
__device__ __forceinline__ void unpack2(long long a, float& lo, float& hi) {
    unsigned l, h;
    asm("mov.b64 {%0, %1}, %2;" : "=r"(l), "=r"(h) : "l"(a));
    lo = __uint_as_float(l); hi = __uint_as_float(h);
}
__device__ __forceinline__ float silu_w(float x, float wc) {
    return x * __fdividef(1.0f, 1.0f + __expf(-x)) * wc;
}

extern "C" __global__ void __launch_bounds__(NTHR, 1) fused_kernel(
    const float* __restrict__ h0, const float* __restrict__ h1,
    const float* __restrict__ pos, const int* __restrict__ batch,
    const float* __restrict__ qW1, const float* __restrict__ qb1,
    const float* __restrict__ qW2, const float* __restrict__ qb2,
    const float* __restrict__ cW1, const float* __restrict__ cb1,
    const float* __restrict__ cW2, const float* __restrict__ cb2,
    const float* __restrict__ muW, float* __restrict__ out)
{
    extern __shared__ float smem[];
    float* sH0P = smem;                         // 21 pairs x 256 floats = 21 KB
    long long* sComb = (long long*)(smem + NPAIRS * 256);  // 18*32*14 ll = 63 KB

    __shared__ float  sPQ[3][14];
    __shared__ float  sPC[3][14];
    __shared__ float  s_mu[ASLOT][3];
    __shared__ float  s_qp[NMOL];
    __shared__ float  s_qmean[NMOL];
    __shared__ double sDD[NWARP];
    __shared__ int    s_last;

    const int tid  = threadIdx.x;
    const int bid  = blockIdx.x;
    const int w    = tid >> 5;
    const int lane = tid & 31;

    const int astart = (bid * NATOMS) / NBLK;
    const int aend   = ((bid + 1) * NATOMS) / NBLK;
    const int acnt   = aend - astart;          // 41 or 42

    if (tid < NMOL) s_qp[tid] = 0.0f;

    // ---- mu loads issued FIRST (latency overlaps h0 staging + sync) --------
    const float4 mw4 = *reinterpret_cast<const float4*>(muW + lane * 4);
    const bool hasB = (w + 24) < acnt;         // atoms w (<24<=acnt) and w+24
    const float* hrA = h1 + (size_t)(astart + w) * 3 * FDIM;
    const float* hrB = h1 + (size_t)(astart + (hasB ? w + 24 : w)) * 3 * FDIM;
    float4 ma0 = *reinterpret_cast<const float4*>(hrA + 0 * FDIM + lane * 4);
    float4 ma1 = *reinterpret_cast<const float4*>(hrA + 1 * FDIM + lane * 4);
    float4 ma2 = *reinterpret_cast<const float4*>(hrA + 2 * FDIM + lane * 4);
    float4 mb0 = *reinterpret_cast<const float4*>(hrB + 0 * FDIM + lane * 4);
    float4 mb1 = *reinterpret_cast<const float4*>(hrB + 1 * FDIM + lane * 4);
    float4 mb2 = *reinterpret_cast<const float4*>(hrB + 2 * FDIM + lane * 4);

    // ---- h0 staging: coalesced LDG.128 -> transformed STS -------------------
    // word index for (atom a, feature f): (a>>1)*256 + f*2 + (a&1)
    {
        const float4 z4 = make_float4(0.f, 0.f, 0.f, 0.f);
        const int a0i = tid >> 5, f0 = (tid & 31) * 4;
        const float4 v0 = (a0i < acnt)
            ? *reinterpret_cast<const float4*>(h0 + (size_t)(astart + a0i) * FDIM + f0) : z4;
        const int idx1 = tid + NTHR;           // second slice (tid < 576)
        const int a1i = idx1 >> 5, f1 = (idx1 & 31) * 4;
        float4 v1 = z4;
        const bool has1 = (idx1 < ASLOT * 32);
        if (has1 && a1i < acnt)
            v1 = *reinterpret_cast<const float4*>(h0 + (size_t)(astart + a1i) * FDIM + f1);

        int base = (a0i >> 1) * 256 + (a0i & 1);
        sH0P[base + (f0 + 0) * 2] = v0.x;
        sH0P[base + (f0 + 1) * 2] = v0.y;
        sH0P[base + (f0 + 2) * 2] = v0.z;
        sH0P[base + (f0 + 3) * 2] = v0.w;
        if (has1) {
            base = (a1i >> 1) * 256 + (a1i & 1);
            sH0P[base + (f1 + 0) * 2] = v1.x;
            sH0P[base + (f1 + 1) * 2] = v1.y;
            sH0P[base + (f1 + 2) * 2] = v1.z;
            sH0P[base + (f1 + 3) * 2] = v1.w;
        }
    }
    __syncthreads();

    // ---- mu dots + reduce (data arrived during staging) --------------------
    {
        float mA[3], mB[3];
        mA[0] = ma0.x * mw4.x + ma0.y * mw4.y + ma0.z * mw4.z + ma0.w * mw4.w;
        mA[1] = ma1.x * mw4.x + ma1.y * mw4.y + ma1.z * mw4.z + ma1.w * mw4.w;
        mA[2] = ma2.x * mw4.x + ma2.y * mw4.y + ma2.z * mw4.z + ma2.w * mw4.w;
        mB[0] = mb0.x * mw4.x + mb0.y * mw4.y + mb0.z * mw4.z + mb0.w * mw4.w;
        mB[1] = mb1.x * mw4.x + mb1.y * mw4.y + mb1.z * mw4.z + mb1.w * mw4.w;
        mB[2] = mb2.x * mw4.x + mb2.y * mw4.y + mb2.z * mw4.z + mb2.w * mw4.w;
        #pragma unroll
        for (int o = 16; o > 0; o >>= 1) {
            #pragma unroll
            for (int d = 0; d < 3; d++) {
                mA[d] += __shfl_down_sync(0xffffffffu, mA[d], o);
                mB[d] += __shfl_down_sync(0xffffffffu, mB[d], o);
            }
        }
        if (lane == 0) {
            s_mu[w][0] = mA[0]; s_mu[w][1] = mA[1]; s_mu[w][2] = mA[2];
            if (hasB) { s_mu[w + 24][0] = mB[0]; s_mu[w + 24][1] = mB[1]; s_mu[w + 24][2] = mB[2]; }
        }
    }

    // ---- MLPs: 24 warps = 2 MLPs x 3 pair-groups x 4 f-quarters ------------
    // Lane owns units {2*lane, 2*lane+1}; weights streamed from L2 via __ldg.
    const int sec = w / 12;                    // 0 = q, 1 = c6
    const int wl  = w % 12;
    const int pg  = wl >> 2;                   // pair-group (7 pairs = 14 atoms)
    const int fq  = wl & 3;                    // f-quarter (8 f4 = 32 features)
    const float* W1 = sec ? cW1 : qW1;
    const float* B1 = sec ? cb1 : qb1;
    const float* W2 = sec ? cW2 : qW2;

    const float2 b1v = __ldg(reinterpret_cast<const float2*>(&B1[2 * lane]));
    const float2 w2v = __ldg(reinterpret_cast<const float2*>(&W2[2 * lane]));

    long long acc[7][2];
    #pragma unroll
    for (int p = 0; p < 7; p++) { acc[p][0] = 0; acc[p][1] = 0; }
    const int pb = pg * 7;
    const int f4beg = fq * 8;

    float2 wbuf[4];
    #pragma unroll
    for (int k = 0; k < 4; k++)
        wbuf[k] = __ldg(reinterpret_cast<const float2*>(
            &W1[(4 * f4beg + k) * HDIM + 2 * lane]));

    #pragma unroll
    for (int fi = 0; fi < 8; fi++) {
        const int f4 = f4beg + fi;
        float2 wc[4];
        #pragma unroll
        for (int k = 0; k < 4; k++) wc[k] = wbuf[k];
        if (fi < 7) {
            #pragma unroll
            for (int k = 0; k < 4; k++)
                wbuf[k] = __ldg(reinterpret_cast<const float2*>(
                    &W1[(4 * (f4 + 1) + k) * HDIM + 2 * lane]));
        }
        const long long u0w0 = dupf(wc[0].x), u1w0 = dupf(wc[0].y);
        const long long u0w1 = dupf(wc[1].x), u1w1 = dupf(wc[1].y);
        const long long u0w2 = dupf(wc[2].x), u1w2 = dupf(wc[2].y);
        const long long u0w3 = dupf(wc[3].x), u1w3 = dupf(wc[3].y);
        #pragma unroll
        for (int p = 0; p < 7; p++) {
            const double2* hp = reinterpret_cast<const double2*>(
                &sH0P[(pb + p) * 256 + f4 * 8]);
            const double2 hA = hp[0];          // feats 4f4, 4f4+1 (atom-pair packed)
            const double2 hB = hp[1];          // feats 4f4+2, 4f4+3
            const long long a0 = __double_as_longlong(hA.x);
            const long long a1 = __double_as_longlong(hA.y);
            const long long a2 = __double_as_longlong(hB.x);
            const long long a3 = __double_as_longlong(hB.y);
            ffma2(acc[p][0], a0, u0w0); ffma2(acc[p][1], a0, u1w0);
            ffma2(acc[p][0], a1, u0w1); ffma2(acc[p][1], a1, u1w1);
            ffma2(acc[p][0], a2, u0w2); ffma2(acc[p][1], a2, u1w2);
            ffma2(acc[p][0], a3, u0w3); ffma2(acc[p][1], a3, u1w3);
        }
    }

    // ---- combine f-quarters: fq 1..3 store, fq 0 finishes ------------------
    __syncthreads();                           // all sH0P reads done (sComb disjoint anyway)
    if (fq != 0) {
        const int slot = (((sec * 3 + pg) * 3 + (fq - 1)) * 32 + lane) * 14;
        #pragma unroll
        for (int p = 0; p < 7; p++) {
            sComb[slot + 2 * p]     = acc[p][0];
            sComb[slot + 2 * p + 1] = acc[p][1];
        }
    }
    __syncthreads();
    if (fq == 0) {
        float v[14];
        #pragma unroll
        for (int p = 0; p < 7; p++) {
            float e0, o0, e1, o1;
            unpack2(acc[p][0], e0, o0);        // unit 2*lane   (even/odd atom)
            unpack2(acc[p][1], e1, o1);        // unit 2*lane+1
            #pragma unroll
            for (int ff = 0; ff < 3; ff++) {
                const int s = (((sec * 3 + pg) * 3 + ff) * 32 + lane) * 14;
                float x, y;
                unpack2(sComb[s + 2 * p], x, y);     e0 += x; o0 += y;
                unpack2(sComb[s + 2 * p + 1], x, y); e1 += x; o1 += y;
            }
            v[2 * p]     = silu_w(e0 + b1v.x, w2v.x) + silu_w(e1 + b1v.y, w2v.y);
            v[2 * p + 1] = silu_w(o0 + b1v.x, w2v.x) + silu_w(o1 + b1v.y, w2v.y);
        }
        #pragma unroll
        for (int k = 0; k < 14; k++) {
            #pragma unroll
            for (int o = 16; o > 0; o >>= 1)
                v[k] += __shfl_down_sync(0xffffffffu, v[k], o);
        }
        if (lane == 0) {
            float (*dst)[14] = sec ? sPC : sPQ;
            #pragma unroll
            for (int k = 0; k < 14; k++) dst[pg][k] = v[k];
        }
    }
    __syncthreads();

    // ---- Pack per-atom data + segment boundaries + molecule q partials -----
    if (tid < acnt) {
        const int grp = tid / 14, idx = tid % 14;
        const float qv  = sPQ[grp][idx] + qb2[0];
        const float cv  = sPC[grp][idx] + cb2[0];
        const float sp  = fmaxf(cv, 0.0f) + log1pf(__expf(-fabsf(cv)));
        const int i = astart + tid;
        const int b = batch[i];
        g_A[i] = make_float4(pos[3 * i], pos[3 * i + 1], pos[3 * i + 2], qv);
        g_B[i] = make_float4(s_mu[tid][0], s_mu[tid][1], s_mu[tid][2], sqrtf(sp));
        if (i == 0 || batch[i - 1] != b) g_segs[b] = i;
        if (i == NATOMS - 1 || batch[i + 1] != b) g_sege[b] = i + 1;
        atomicAdd(&s_qp[b], qv);
    }
    __syncthreads();
    if (tid < NMOL && s_qp[tid] != 0.0f) atomicAdd(&g_qsumF[tid], s_qp[tid]);

    grid_barrier();

    // ---- qmean staging: one LDG round --------------------------------------
    if (tid < NMOL) {
        const int cnt = g_sege[tid] - g_segs[tid];
        s_qmean[tid] = (cnt > 0) ? g_qsumF[tid] / (float)cnt : 0.0f;
    }
    __syncthreads();

    // ---- Pairwise energy (i<j; all terms symmetric), strided + pipelined ---
    double acc2 = 0.0;
    for (int i = bid * NWARP + w; i < NATOMS; i += NWTOT) {
        const int b  = batch[i];
        const int e0 = g_sege[b];
        const float qm = s_qmean[b];

        const float4 Ai = g_A[i];
        const float4 Bi = g_B[i];
        const float qi = Ai.w - qm;

        float facc = 0.0f;
        int j = i + 1 + lane;
        if (j < e0) {
            float4 Aj = g_A[j];
            float4 Bj = g_B[j];
            while (true) {
                const int jn = j + 32;
                float4 An, Bn;
                if (jn < e0) { An = g_A[jn]; Bn = g_B[jn]; }   // prefetch

                const float dx = Ai.x - Aj.x;
                const float dy = Ai.y - Aj.y;
                const float dz = Ai.z - Aj.z;
                const float d2r  = dx * dx + dy * dy + dz * dz;
                const float d2   = d2r + 1e-8f;
                const float invd = rsqrtf(d2);                    // MUFU 1
                const float dist = d2 * invd;

                const float qj    = Aj.w - qm;
                const float taper = 1.0f - __expf(-0.5f * dist);  // MUFU 2
                const float ec    = qi * qj * invd * taper * 14.399f;

                const float r6    = d2r * d2r * d2r;
                const float aden  = r6 + 20.0f;
                const float bden  = d2r * dist + 10.0f;
                const float invab = __fdividef(1.0f, aden * bden); // MUFU 3

                const float ev = -Bi.w * Bj.w * (invab * bden);

                const float mumu = Bi.x * Bj.x + Bi.y * Bj.y + Bi.z * Bj.z;
                const float di   = (Bi.x * dx + Bi.y * dy + Bi.z * dz) * invd;
                const float dj   = (Bj.x * dx + Bj.y * dy + Bj.z * dz) * invd;
                const float ed   = (mumu - 3.0f * di * dj) * (invab * aden);

                facc += ec + ev + ed;

                if (jn >= e0) break;
                Aj = An; Bj = Bn; j = jn;
            }
        }
        acc2 += (double)facc;
    }

    #pragma unroll
    for (int o = 16; o > 0; o >>= 1)
        acc2 += __shfl_down_sync(0xffffffffu, acc2, o);
    if (lane == 0) sDD[w] = acc2;
    __syncthreads();
    if (tid == 0) {
        double ts = 0.0;
        #pragma unroll
        for (int k = 0; k < NWARP; k++) ts += sDD[k];
        g_partial[bid] = ts;
        __threadfence();
        s_last = (atomicAdd(&g_done, 1) == NBLK - 1) ? 1 : 0;
    }
    __syncthreads();

    // ---- Last-arriving block: reset replay state, reduce, write output -----
    if (s_last) {
        __threadfence();
        if (tid == 0) g_done = 0;
        if (tid < NMOL) g_qsumF[tid] = 0.0f;   // all readers finished (ticket)
        double v = (tid < NBLK) ? g_partial[tid] : 0.0;
        #pragma unroll
        for (int o = 16; o > 0; o >>= 1)
            v += __shfl_down_sync(0xffffffffu, v, o);
        if (lane == 0 && w < 5) sDD[w] = v;
        __syncthreads();
        if (tid == 0) {
            double tot = 0.0;
            #pragma unroll
            for (int k = 0; k < 5; k++) tot += sDD[k];
            out[0] = (float)tot;               // LONG_RANGE_SCALE = 1.0
        }
    }
}

// ---------------------------------------------------------------------------
extern "C" void kernel_launch(void* const* d_in, const int* in_sizes, int n_in,
                              void* d_out, int out_size) {
    const float* h0    = (const float*)d_in[0];
    const float* h1    = (const float*)d_in[1];
    const float* pos   = (const float*)d_in[2];
    const int*   batch = (const int*)  d_in[3];
    const float* qW1   = (const float*)d_in[4];
    const float* qb1   = (const float*)d_in[5];
    const float* qW2   = (const float*)d_in[6];
    const float* qb2   = (const float*)d_in[7];
    const float* cW1   = (const float*)d_in[8];
    const float* cb1   = (const float*)d_in[9];
    const float* cW2   = (const float*)d_in[10];
    const float* cb2   = (const float*)d_in[11];
    const float* muW   = (const float*)d_in[12];

    // sH0P (21*256 floats) + sComb (18*32*14 long long)
    const int smem_bytes = NPAIRS * 256 * 4 + 18 * 32 * 14 * 8;   // 84 KB
    cudaFuncSetAttribute(fused_kernel,
                         cudaFuncAttributeMaxDynamicSharedMemorySize, smem_bytes);
    fused_kernel<<<NBLK, NTHR, smem_bytes>>>(
        h0, h1, pos, batch,
        qW1, qb1, qW2, qb2,
        cW1, cb1, cW2, cb2,
        muW, (float*)d_out);
}